// round 9
// baseline (speedup 1.0000x reference)
#include <cuda_runtime.h>
#include <cuda_bf16.h>
#include <cstdint>
#include <math.h>

// DiagBlockAttention b=16,t=8192,e=256,block=128 — mma.sync bf16 hi/lo split.
// R9: 512-thread CTAs (16 warps, 16x64 S-tiles) -> 32 warps/SM; 16-row causal
// skip; single-sync direct staging.
// d_out = O [b,t,256] fp32 ++ A_flat [b,t,128] fp32.

namespace {
constexpr int Tt = 8192, Ee = 256, BSz = 128, NBk = 64;
constexpr float SCALE = 0.0625f;
constexpr int EC = 32;           // phase-1 e-chunk
constexpr int VC = 32;           // phase-3 e-chunk
constexpr int NT = 512;          // threads per CTA

// SMEM byte map
constexpr int RED_M = 0;         // 256 f32
constexpr int RED_S = 1024;      // 256 f32
constexpr int REG0  = 2048;
// phase 1: double-buffered bf16 Q/K hi/lo tiles [128 r][32 c], 64B rows (swz64)
//   per buffer: QH +0, QL +8192, KH +16384, KL +24576 ; buffer stride 32768
// phase 2/3: A hi/lo [128 m][128 k] bf16, 256B rows (swz256) — overlaps P1 bufs
constexpr int AHs = REG0, ALs = REG0 + 32768;
// phase 3: V^T hi/lo [32 e][128 tok] bf16, 256B rows (swz256), double buffered
//   at VB0 + bs*16384 (VH +0, VL +8192) — separate region (untouched in P1)
constexpr int VB0 = REG0 + 65536;
constexpr int SMEM_BYTES = REG0 + 98304;   // 100352 -> 2 CTAs/SM
}

__device__ __forceinline__ uint32_t swz64(uint32_t o)  { return o ^ ((o >> 3) & 0x30u); }
__device__ __forceinline__ uint32_t swz256(uint32_t o) { return o ^ ((o >> 4) & 0x70u); }

__device__ __forceinline__ uint32_t smem_u32(const void* p) {
    uint32_t a;
    asm("{ .reg .u64 t; cvta.to.shared.u64 t, %1; cvt.u32.u64 %0, t; }" : "=r"(a) : "l"(p));
    return a;
}

__device__ __forceinline__ void ldmx4(uint32_t r[4], uint32_t addr) {
    asm volatile("ldmatrix.sync.aligned.m8n8.x4.shared.b16 {%0,%1,%2,%3}, [%4];"
                 : "=r"(r[0]), "=r"(r[1]), "=r"(r[2]), "=r"(r[3]) : "r"(addr));
}

__device__ __forceinline__ void mma16816(float c[4], const uint32_t a[4],
                                         uint32_t b0, uint32_t b1) {
    asm volatile("mma.sync.aligned.m16n8k16.row.col.f32.bf16.bf16.f32 "
                 "{%0,%1,%2,%3},{%4,%5,%6,%7},{%8,%9},{%0,%1,%2,%3};"
                 : "+f"(c[0]), "+f"(c[1]), "+f"(c[2]), "+f"(c[3])
                 : "r"(a[0]), "r"(a[1]), "r"(a[2]), "r"(a[3]), "r"(b0), "r"(b1));
}

// Truncation-based hi/lo split of two fp32 into packed bf16x2.
__device__ __forceinline__ void split2t(float x, float y, uint32_t& H, uint32_t& L) {
    uint32_t ux = __float_as_uint(x), uy = __float_as_uint(y);
    asm("prmt.b32 %0, %1, %2, 0x7632;" : "=r"(H) : "r"(ux), "r"(uy));
    float tx = __uint_as_float(ux & 0xFFFF0000u);
    float ty = __uint_as_float(uy & 0xFFFF0000u);
    asm("cvt.rn.bf16x2.f32 %0, %1, %2;" : "=r"(L) : "f"(y - ty), "f"(x - tx));
}

__global__ void __launch_bounds__(NT, 2)
diag_block_attn_mma(const float* __restrict__ Q, const float* __restrict__ K,
                    const float* __restrict__ V, float* __restrict__ Out,
                    float* __restrict__ Afl)
{
    extern __shared__ char smc[];
    const uint32_t sb = smem_u32(smc);
    float* redM = reinterpret_cast<float*>(smc + RED_M);
    float* redS = reinterpret_cast<float*>(smc + RED_S);

    const int tid = threadIdx.x;
    const int wid = tid >> 5;        // 0..15
    const int lid = tid & 31;
    const int g   = lid >> 2;
    const int tg  = lid & 3;
    const int wm  = wid >> 1;        // warp row (0..7): rows wm*16..+15
    const int wn  = wid & 1;         // warp col (0..1): cols wn*64..+63
    const int lr  = lid & 15;
    const int lc  = (lid >> 4) * 8;  // ldmatrix col-block (elements)
    const int n   = blockIdx.x;
    const int b   = blockIdx.y;
    const long base = ((long)b * Tt + (long)n * BSz) * Ee;

    // Causal tile bound: n16-tile ng kept iff wn*64+16*ng <= wm*16+15.
    const int dtri  = wm * 16 + 15 - wn * 64;
    const int ngEnd = (dtri < 0) ? 0 : min(4, (dtri >> 4) + 1);

    // ---- phase-1 staging: chunk c (32 e) -> buffer bs (direct split) ----
    auto stage1 = [&](int c, int bs) {
        const float* Qg = Q + base + c * EC;
        const float* Kg = K + base + c * EC;
        char* bb = smc + REG0 + bs * 32768;
        #pragma unroll
        for (int u = 0; u < 2; ++u) {
            int idx = tid + NT * u;        // 0..1023
            int r   = idx >> 3;            // 0..127
            int ce  = (idx & 7) << 2;      // 0..28
            float4 q = *reinterpret_cast<const float4*>(Qg + (long)r * Ee + ce);
            float4 k = *reinterpret_cast<const float4*>(Kg + (long)r * Ee + ce);
            uint32_t qh0, ql0, qh1, ql1, kh0, kl0, kh1, kl1;
            split2t(q.x, q.y, qh0, ql0); split2t(q.z, q.w, qh1, ql1);
            split2t(k.x, k.y, kh0, kl0); split2t(k.z, k.w, kh1, kl1);
            uint32_t off = swz64((uint32_t)(r * 64 + ce * 2));
            *reinterpret_cast<uint2*>(bb + off)         = make_uint2(qh0, qh1);
            *reinterpret_cast<uint2*>(bb + 8192 + off)  = make_uint2(ql0, ql1);
            *reinterpret_cast<uint2*>(bb + 16384 + off) = make_uint2(kh0, kh1);
            *reinterpret_cast<uint2*>(bb + 24576 + off) = make_uint2(kl0, kl1);
        }
    };

    // ---- phase-3 V staging: chunk nc (32 e) -> buffer bs (transposed) ----
    auto stage3 = [&](int nc, int bs) {
        char* bb = smc + VB0 + bs * 16384;
        {
            int unit = tid;                 // 0..511
            int l    = unit & 31;
            int grp  = unit >> 5;           // 0..15
            int c4i  = grp & 7, khi = grp >> 3;
            int k    = 2 * l + 64 * khi;    // even token
            int e0   = 4 * c4i;
            const float* vg = V + base + (long)k * Ee + nc * VC + e0;
            float4 v0 = *reinterpret_cast<const float4*>(vg);
            float4 v1 = *reinterpret_cast<const float4*>(vg + Ee);
            const float* a0 = reinterpret_cast<const float*>(&v0);
            const float* a1 = reinterpret_cast<const float*>(&v1);
            #pragma unroll
            for (int j = 0; j < 4; ++j) {
                uint32_t H, L;
                split2t(a0[j], a1[j], H, L);
                uint32_t off = swz256((uint32_t)((e0 + j) * 256 + k * 2));
                *reinterpret_cast<uint32_t*>(bb + off)        = H;
                *reinterpret_cast<uint32_t*>(bb + 8192 + off) = L;
            }
        }
    };

    // ================= Phase 1: S = Q K^T (3-pass hi/lo, pipelined) ==========
    float acc[8][4];
    #pragma unroll
    for (int nt = 0; nt < 8; ++nt)
        #pragma unroll
        for (int cc = 0; cc < 4; ++cc) acc[nt][cc] = 0.f;

    stage1(0, 0);
    __syncthreads();
    #pragma unroll 1
    for (int c = 0; c < 8; ++c) {
        if (c + 1 < 8) stage1(c + 1, (c + 1) & 1);
        if (ngEnd > 0) {
            const uint32_t bb = sb + REG0 + (c & 1) * 32768;
            #pragma unroll
            for (int ks = 0; ks < 2; ++ks) {
                const int colB = (lc + ks * 16) * 2;
                uint32_t qhf[4], qlf[4];
                {
                    uint32_t off = swz64((uint32_t)((wm * 16 + lr) * 64 + colB));
                    ldmx4(qhf, bb + off);
                    ldmx4(qlf, bb + 8192 + off);
                }
                #pragma unroll
                for (int ng = 0; ng < 4; ++ng) {
                    if (ng < ngEnd) {
                        uint32_t off = swz64((uint32_t)((wn * 64 + ng * 16 + lr) * 64 + colB));
                        uint32_t kh4[4], kl4[4];
                        ldmx4(kh4, bb + 16384 + off);
                        ldmx4(kl4, bb + 24576 + off);
                        mma16816(acc[2 * ng],     qhf, kh4[0], kh4[2]);
                        mma16816(acc[2 * ng + 1], qhf, kh4[1], kh4[3]);
                        mma16816(acc[2 * ng],     qhf, kl4[0], kl4[2]);
                        mma16816(acc[2 * ng + 1], qhf, kl4[1], kl4[3]);
                        mma16816(acc[2 * ng],     qlf, kh4[0], kh4[2]);
                        mma16816(acc[2 * ng + 1], qlf, kh4[1], kh4[3]);
                    }
                }
            }
        }
        __syncthreads();
    }

    // ================= Phase 2: mask + softmax =================
    float rmax[2] = {-INFINITY, -INFINITY};
    #pragma unroll
    for (int nt = 0; nt < 8; ++nt)
        #pragma unroll
        for (int cc = 0; cc < 4; ++cc) {
            int row = wm * 16 + (cc >> 1) * 8 + g;
            int col = wn * 64 + nt * 8 + 2 * tg + (cc & 1);
            float v = (col <= row) ? acc[nt][cc] * SCALE : -INFINITY;
            acc[nt][cc] = v;
            rmax[cc >> 1] = fmaxf(rmax[cc >> 1], v);
        }
    #pragma unroll
    for (int rh = 0; rh < 2; ++rh) {
        float v = rmax[rh];
        v = fmaxf(v, __shfl_xor_sync(0xffffffffu, v, 1));
        v = fmaxf(v, __shfl_xor_sync(0xffffffffu, v, 2));
        if (tg == 0) redM[wn * 128 + wm * 16 + rh * 8 + g] = v;
    }
    __syncthreads();

    float rm[2], rsum[2] = {0.f, 0.f};
    #pragma unroll
    for (int rh = 0; rh < 2; ++rh) {
        int row = wm * 16 + rh * 8 + g;
        rm[rh] = fmaxf(redM[row], redM[128 + row]);
    }
    #pragma unroll
    for (int nt = 0; nt < 8; ++nt)
        #pragma unroll
        for (int cc = 0; cc < 4; ++cc) {
            float p = __expf(acc[nt][cc] - rm[cc >> 1]);
            acc[nt][cc] = p;
            rsum[cc >> 1] += p;
        }
    #pragma unroll
    for (int rh = 0; rh < 2; ++rh) {
        float s = rsum[rh];
        s += __shfl_xor_sync(0xffffffffu, s, 1);
        s += __shfl_xor_sync(0xffffffffu, s, 2);
        if (tg == 0) redS[wn * 128 + wm * 16 + rh * 8 + g] = s;
    }

    // Pre-stage V chunk 0 (VB0 region is untouched by phase 1 — no hazard);
    // gmem latency hides behind the softmax math + barrier.
    stage3(0, 0);
    __syncthreads();

    float rinv[2];
    #pragma unroll
    for (int rh = 0; rh < 2; ++rh) {
        int row = wm * 16 + rh * 8 + g;
        rinv[rh] = 1.f / (redS[row] + redS[128 + row]);
    }

    // Normalize; A -> gmem (fp32) and smem hi/lo bf16 (overwrites P1 buffers —
    // ordered by the barrier above).
    #pragma unroll
    for (int nt = 0; nt < 8; ++nt)
        #pragma unroll
        for (int rh = 0; rh < 2; ++rh) {
            float a0 = acc[nt][rh * 2]     * rinv[rh];
            float a1 = acc[nt][rh * 2 + 1] * rinv[rh];
            int row = wm * 16 + rh * 8 + g;
            int col = wn * 64 + nt * 8 + 2 * tg;
            uint32_t H, L;
            split2t(a0, a1, H, L);
            uint32_t off = swz256((uint32_t)(row * 256 + col * 2));
            *reinterpret_cast<uint32_t*>(smc + AHs + off) = H;
            *reinterpret_cast<uint32_t*>(smc + ALs + off) = L;
            if (Afl) {
                *reinterpret_cast<float2*>(
                    Afl + ((long)b * Tt + (long)n * BSz + row) * BSz + col) =
                    make_float2(a0, a1);
            }
        }
    __syncthreads();   // A tiles + V chunk 0 ready

    // ================= Phase 3: O = A V (8 e-chunks of 32, pipelined) ========
    // Warp (wm,wn): rows wm*16..+15, e-columns nc*32 + wn*16..+15.
    #pragma unroll 1
    for (int nc = 0; nc < 8; ++nc) {
        if (nc + 1 < 8) stage3(nc + 1, (nc + 1) & 1);
        const uint32_t vb = sb + VB0 + (nc & 1) * 16384;

        float o3[2][4];
        #pragma unroll
        for (int nt = 0; nt < 2; ++nt)
            #pragma unroll
            for (int cc = 0; cc < 4; ++cc) o3[nt][cc] = 0.f;

        #pragma unroll
        for (int ks = 0; ks < 8; ++ks) {
            const int colB = (lc + ks * 16) * 2;
            uint32_t ahf[4], alf[4];
            {
                uint32_t off = swz256((uint32_t)((wm * 16 + lr) * 256 + colB));
                ldmx4(ahf, sb + AHs + off);
                ldmx4(alf, sb + ALs + off);
            }
            uint32_t offv = swz256((uint32_t)((wn * 16 + lr) * 256 + colB));
            uint32_t vh4[4], vl4[4];
            ldmx4(vh4, vb + offv);
            ldmx4(vl4, vb + 8192 + offv);
            mma16816(o3[0], ahf, vh4[0], vh4[2]);
            mma16816(o3[1], ahf, vh4[1], vh4[3]);
            mma16816(o3[0], ahf, vl4[0], vl4[2]);
            mma16816(o3[1], ahf, vl4[1], vl4[3]);
            mma16816(o3[0], alf, vh4[0], vh4[2]);
            mma16816(o3[1], alf, vh4[1], vh4[3]);
        }

        #pragma unroll
        for (int nt = 0; nt < 2; ++nt)
            #pragma unroll
            for (int rh = 0; rh < 2; ++rh) {
                int row = wm * 16 + rh * 8 + g;
                int col = nc * VC + wn * 16 + nt * 8 + 2 * tg;
                *reinterpret_cast<float2*>(Out + base + (long)row * Ee + col) =
                    make_float2(o3[nt][rh * 2], o3[nt][rh * 2 + 1]);
            }
        __syncthreads();
    }
}

extern "C" void kernel_launch(void* const* d_in, const int* in_sizes, int n_in,
                              void* d_out, int out_size)
{
    const float* Q = (const float*)d_in[0];
    const float* K = (const float*)d_in[1];
    const float* V = (const float*)d_in[2];
    float* out = (float*)d_out;

    const int b = in_sizes[0] / (Tt * Ee);
    const long out_elems = (long)b * Tt * Ee;
    const long a_elems   = (long)b * Tt * BSz;
    float* Afl = ((long)out_size >= out_elems + a_elems) ? (out + out_elems) : nullptr;

    cudaFuncSetAttribute(diag_block_attn_mma,
                         cudaFuncAttributeMaxDynamicSharedMemorySize, SMEM_BYTES);
    dim3 grid(NBk, b);
    diag_block_attn_mma<<<grid, NT, SMEM_BYTES>>>(Q, K, V, out, Afl);
}

// round 10
// speedup vs baseline: 1.2005x; 1.2005x over previous
#include <cuda_runtime.h>
#include <cuda_bf16.h>
#include <cstdint>
#include <math.h>

// DiagBlockAttention b=16,t=8192,e=256,block=128 — mma.sync bf16 hi/lo split.
// R10: 16-row warp bands; A kept in registers (C-frag == A-frag); shuffle-only
// softmax; causal skip in both GEMMs; cp.async phase-1; double-buffered V.
// d_out = O [b,t,256] fp32 ++ A_flat [b,t,128] fp32.

namespace {
constexpr int Tt = 8192, Ee = 256, BSz = 128, NBk = 64;
constexpr float SCALE = 0.0625f;
constexpr int EC = 32;           // phase-1 e-chunk
constexpr int VC = 32;           // phase-3 e-chunk
constexpr int NT = 256;

// SMEM byte map
// bf16 Q/K hi/lo tiles [128 r][32 c], 64B rows (swz64), single buffer:
//   QH +0, QL +8192, KH +16384, KL +24576  (32 KB)
constexpr int BF0  = 0;
// raw fp32 staging, double-buffered: RAW0 + bs*32768 (Q +0, K +16384)
constexpr int RAW0 = 32768;
// phase 3: V^T hi/lo [32 e][128 tok] bf16, 256B rows (swz256), double buffered
//   at VB0 + bs*16384 (VH +0, VL +8192) — overlays raw[0] (dead by then)
constexpr int VB0  = 32768;
constexpr int SMEM_BYTES = 98304;   // 96 KB -> 2 CTAs/SM
}

__device__ __forceinline__ uint32_t swz64(uint32_t o)  { return o ^ ((o >> 3) & 0x30u); }
__device__ __forceinline__ uint32_t swz256(uint32_t o) { return o ^ ((o >> 4) & 0x70u); }

__device__ __forceinline__ uint32_t smem_u32(const void* p) {
    uint32_t a;
    asm("{ .reg .u64 t; cvta.to.shared.u64 t, %1; cvt.u32.u64 %0, t; }" : "=r"(a) : "l"(p));
    return a;
}

__device__ __forceinline__ void cpasync16(uint32_t dst, const void* src) {
    asm volatile("cp.async.ca.shared.global [%0], [%1], 16;" :: "r"(dst), "l"(src) : "memory");
}
__device__ __forceinline__ void cpcommit() {
    asm volatile("cp.async.commit_group;" ::: "memory");
}
template <int N>
__device__ __forceinline__ void cpwait() {
    asm volatile("cp.async.wait_group %0;" :: "n"(N) : "memory");
}

__device__ __forceinline__ void ldmx4(uint32_t r[4], uint32_t addr) {
    asm volatile("ldmatrix.sync.aligned.m8n8.x4.shared.b16 {%0,%1,%2,%3}, [%4];"
                 : "=r"(r[0]), "=r"(r[1]), "=r"(r[2]), "=r"(r[3]) : "r"(addr));
}

__device__ __forceinline__ void mma16816(float c[4], const uint32_t a[4],
                                         uint32_t b0, uint32_t b1) {
    asm volatile("mma.sync.aligned.m16n8k16.row.col.f32.bf16.bf16.f32 "
                 "{%0,%1,%2,%3},{%4,%5,%6,%7},{%8,%9},{%0,%1,%2,%3};"
                 : "+f"(c[0]), "+f"(c[1]), "+f"(c[2]), "+f"(c[3])
                 : "r"(a[0]), "r"(a[1]), "r"(a[2]), "r"(a[3]), "r"(b0), "r"(b1));
}

// Truncation-based hi/lo split of two fp32 into packed bf16x2.
__device__ __forceinline__ void split2t(float x, float y, uint32_t& H, uint32_t& L) {
    uint32_t ux = __float_as_uint(x), uy = __float_as_uint(y);
    asm("prmt.b32 %0, %1, %2, 0x7632;" : "=r"(H) : "r"(ux), "r"(uy));
    float tx = __uint_as_float(ux & 0xFFFF0000u);
    float ty = __uint_as_float(uy & 0xFFFF0000u);
    asm("cvt.rn.bf16x2.f32 %0, %1, %2;" : "=r"(L) : "f"(y - ty), "f"(x - tx));
}

__global__ void __launch_bounds__(NT, 2)
diag_block_attn_mma(const float* __restrict__ Q, const float* __restrict__ K,
                    const float* __restrict__ V, float* __restrict__ Out,
                    float* __restrict__ Afl)
{
    extern __shared__ char smc[];
    const uint32_t sb = smem_u32(smc);

    const int tid = threadIdx.x;
    const int wid = tid >> 5;        // 0..7
    const int lid = tid & 31;
    const int g   = lid >> 2;
    const int tg  = lid & 3;
    const int wm  = wid;             // warp row band: rows wm*16..+15
    const int lr  = lid & 15;
    const int lc  = (lid >> 4) * 8;  // ldmatrix col-block (elements)
    const int n   = blockIdx.x;
    const int b   = blockIdx.y;
    const long base = ((long)b * Tt + (long)n * BSz) * Ee;

    // Causal: col-tile ng (16 wide) kept iff 16*ng <= 16*wm+15  ->  ng <= wm.
    const int ngEnd = wm + 1;        // also phase-3 ksEnd

    // ---- phase-1: cp.async raw fp32 chunk c -> raw buffer bs ----
    auto cpstage1 = [&](int c, int bs) {
        const float* Qg = Q + base + c * EC;
        const float* Kg = K + base + c * EC;
        const uint32_t rw = sb + RAW0 + bs * 32768;
        #pragma unroll
        for (int u = 0; u < 4; ++u) {
            int idx = tid + NT * u;        // 0..1023
            int r   = idx >> 3;            // 0..127
            int s   = idx & 7;             // 16B segment
            cpasync16(rw + r * 128 + s * 16,         Qg + (long)r * Ee + s * 4);
            cpasync16(rw + 16384 + r * 128 + s * 16, Kg + (long)r * Ee + s * 4);
        }
        cpcommit();
    };

    // ---- phase-1: convert raw buffer bs -> bf16 hi/lo tiles ----
    auto convert1 = [&](int bs) {
        const char* rw = smc + RAW0 + bs * 32768;
        #pragma unroll
        for (int u = 0; u < 4; ++u) {
            int idx = tid + NT * u;        // 0..1023
            int r   = idx >> 3;
            int ce  = (idx & 7) << 2;
            float4 q = *reinterpret_cast<const float4*>(rw + r * 128 + ce * 4);
            float4 k = *reinterpret_cast<const float4*>(rw + 16384 + r * 128 + ce * 4);
            uint32_t qh0, ql0, qh1, ql1, kh0, kl0, kh1, kl1;
            split2t(q.x, q.y, qh0, ql0); split2t(q.z, q.w, qh1, ql1);
            split2t(k.x, k.y, kh0, kl0); split2t(k.z, k.w, kh1, kl1);
            uint32_t off = swz64((uint32_t)(r * 64 + ce * 2));
            *reinterpret_cast<uint2*>(smc + BF0 + off)         = make_uint2(qh0, qh1);
            *reinterpret_cast<uint2*>(smc + BF0 + 8192 + off)  = make_uint2(ql0, ql1);
            *reinterpret_cast<uint2*>(smc + BF0 + 16384 + off) = make_uint2(kh0, kh1);
            *reinterpret_cast<uint2*>(smc + BF0 + 24576 + off) = make_uint2(kl0, kl1);
        }
    };

    // ---- phase-3 V staging: chunk nc (32 e) -> buffer bs (transposed) ----
    auto stage3 = [&](int nc, int bs) {
        char* bb = smc + VB0 + bs * 16384;
        #pragma unroll
        for (int u = 0; u < 2; ++u) {
            int unit = tid + NT * u;        // 0..511
            int l    = unit & 31;
            int grp  = unit >> 5;           // 0..15
            int c4i  = grp & 7, khi = grp >> 3;
            int k    = 2 * l + 64 * khi;    // even token
            int e0   = 4 * c4i;
            const float* vg = V + base + (long)k * Ee + nc * VC + e0;
            float4 v0 = *reinterpret_cast<const float4*>(vg);
            float4 v1 = *reinterpret_cast<const float4*>(vg + Ee);
            const float* a0 = reinterpret_cast<const float*>(&v0);
            const float* a1 = reinterpret_cast<const float*>(&v1);
            #pragma unroll
            for (int j = 0; j < 4; ++j) {
                uint32_t H, L;
                split2t(a0[j], a1[j], H, L);
                uint32_t off = swz256((uint32_t)((e0 + j) * 256 + k * 2));
                *reinterpret_cast<uint32_t*>(bb + off)        = H;
                *reinterpret_cast<uint32_t*>(bb + 8192 + off) = L;
            }
        }
    };

    // ================= Phase 1: S = Q K^T (3-pass hi/lo, cp.async pipe) ======
    float acc[16][4];
    #pragma unroll
    for (int nt = 0; nt < 16; ++nt)
        #pragma unroll
        for (int cc = 0; cc < 4; ++cc) acc[nt][cc] = 0.f;

    cpstage1(0, 0);
    #pragma unroll 1
    for (int c = 0; c < 8; ++c) {
        if (c + 1 < 8) { cpstage1(c + 1, (c + 1) & 1); cpwait<1>(); }
        else           { cpwait<0>(); }
        __syncthreads();   // all warps done with prior MMA (bf16 buf reusable)
        convert1(c & 1);
        __syncthreads();   // bf16 tiles ready
        const uint32_t bb = sb + BF0;
        #pragma unroll
        for (int ks = 0; ks < 2; ++ks) {
            const int colB = (lc + ks * 16) * 2;
            uint32_t qhf[4], qlf[4];
            {
                uint32_t off = swz64((uint32_t)((wm * 16 + lr) * 64 + colB));
                ldmx4(qhf, bb + off);
                ldmx4(qlf, bb + 8192 + off);
            }
            #pragma unroll
            for (int ng = 0; ng < 8; ++ng) {
                if (ng < ngEnd) {
                    uint32_t off = swz64((uint32_t)((ng * 16 + lr) * 64 + colB));
                    uint32_t kh4[4], kl4[4];
                    ldmx4(kh4, bb + 16384 + off);
                    ldmx4(kl4, bb + 24576 + off);
                    mma16816(acc[2 * ng],     qhf, kh4[0], kh4[2]);
                    mma16816(acc[2 * ng + 1], qhf, kh4[1], kh4[3]);
                    mma16816(acc[2 * ng],     qhf, kl4[0], kl4[2]);
                    mma16816(acc[2 * ng + 1], qhf, kl4[1], kl4[3]);
                    mma16816(acc[2 * ng],     qlf, kh4[0], kh4[2]);
                    mma16816(acc[2 * ng + 1], qlf, kh4[1], kh4[3]);
                }
            }
        }
    }

    // ================= Phase 2: shuffle-only softmax =================
    const int nValid = 2 * ngEnd;    // live n8-tiles for this warp
    float rmax[2] = {-INFINITY, -INFINITY};
    #pragma unroll
    for (int nt = 0; nt < 16; ++nt) {
        if (nt < nValid) {
            #pragma unroll
            for (int cc = 0; cc < 4; ++cc) {
                int row = wm * 16 + (cc >> 1) * 8 + g;
                int col = nt * 8 + 2 * tg + (cc & 1);
                float v = (col <= row) ? acc[nt][cc] * SCALE : -INFINITY;
                acc[nt][cc] = v;
                rmax[cc >> 1] = fmaxf(rmax[cc >> 1], v);
            }
        }
    }
    #pragma unroll
    for (int rh = 0; rh < 2; ++rh) {
        rmax[rh] = fmaxf(rmax[rh], __shfl_xor_sync(0xffffffffu, rmax[rh], 1));
        rmax[rh] = fmaxf(rmax[rh], __shfl_xor_sync(0xffffffffu, rmax[rh], 2));
    }
    float rsum[2] = {0.f, 0.f};
    #pragma unroll
    for (int nt = 0; nt < 16; ++nt) {
        if (nt < nValid) {
            #pragma unroll
            for (int cc = 0; cc < 4; ++cc) {
                float p = __expf(acc[nt][cc] - rmax[cc >> 1]);
                acc[nt][cc] = p;
                rsum[cc >> 1] += p;
            }
        } else {
            #pragma unroll
            for (int cc = 0; cc < 4; ++cc) acc[nt][cc] = 0.f;
        }
    }
    #pragma unroll
    for (int rh = 0; rh < 2; ++rh) {
        rsum[rh] += __shfl_xor_sync(0xffffffffu, rsum[rh], 1);
        rsum[rh] += __shfl_xor_sync(0xffffffffu, rsum[rh], 2);
    }
    const float rinv[2] = {1.f / rsum[0], 1.f / rsum[1]};

    // Pre-stage V chunk 0 (VB0 = raw[0], dead since c=7 barriers).
    stage3(0, 0);

    // Normalize; A -> gmem (fp32) and A-operand fragments IN REGISTERS
    // (C-frag layout == row-major A-frag layout for m16n8k16).
    uint32_t Ah[8][4], Al[8][4];
    #pragma unroll
    for (int t = 0; t < 8; ++t) {
        #pragma unroll
        for (int half = 0; half < 2; ++half) {
            int nt = 2 * t + half;
            #pragma unroll
            for (int rh = 0; rh < 2; ++rh) {
                float a0 = acc[nt][rh * 2]     * rinv[rh];
                float a1 = acc[nt][rh * 2 + 1] * rinv[rh];
                uint32_t H, L;
                split2t(a0, a1, H, L);
                Ah[t][half * 2 + rh] = H;
                Al[t][half * 2 + rh] = L;
                if (Afl) {
                    int row = wm * 16 + rh * 8 + g;
                    int col = nt * 8 + 2 * tg;
                    *reinterpret_cast<float2*>(
                        Afl + ((long)b * Tt + (long)n * BSz + row) * BSz + col) =
                        make_float2(a0, a1);
                }
            }
        }
    }
    __syncthreads();   // V chunk 0 staged (and all warps past phase-1 reads)

    // ================= Phase 3: O = A V (8 e-chunks of 32, pipelined) ========
    // Warp wm: rows wm*16..+15, all 32 e of the chunk; skip zero A k-tiles.
    #pragma unroll 1
    for (int nc = 0; nc < 8; ++nc) {
        if (nc + 1 < 8) stage3(nc + 1, (nc + 1) & 1);
        const uint32_t vb = sb + VB0 + (nc & 1) * 16384;

        float o3[4][4];
        #pragma unroll
        for (int nt = 0; nt < 4; ++nt)
            #pragma unroll
            for (int cc = 0; cc < 4; ++cc) o3[nt][cc] = 0.f;

        #pragma unroll
        for (int ks = 0; ks < 8; ++ks) {
            if (ks < ngEnd) {
                const int colB = (lc + ks * 16) * 2;
                #pragma unroll
                for (int et = 0; et < 2; ++et) {
                    uint32_t off = swz256((uint32_t)((et * 16 + lr) * 256 + colB));
                    uint32_t vh4[4], vl4[4];
                    ldmx4(vh4, vb + off);
                    ldmx4(vl4, vb + 8192 + off);
                    mma16816(o3[2 * et],     Ah[ks], vh4[0], vh4[2]);
                    mma16816(o3[2 * et + 1], Ah[ks], vh4[1], vh4[3]);
                    mma16816(o3[2 * et],     Ah[ks], vl4[0], vl4[2]);
                    mma16816(o3[2 * et + 1], Ah[ks], vl4[1], vl4[3]);
                    mma16816(o3[2 * et],     Al[ks], vh4[0], vh4[2]);
                    mma16816(o3[2 * et + 1], Al[ks], vh4[1], vh4[3]);
                }
            }
        }

        #pragma unroll
        for (int nt = 0; nt < 4; ++nt)
            #pragma unroll
            for (int rh = 0; rh < 2; ++rh) {
                int row = wm * 16 + rh * 8 + g;
                int col = nc * VC + nt * 8 + 2 * tg;
                *reinterpret_cast<float2*>(Out + base + (long)row * Ee + col) =
                    make_float2(o3[nt][rh * 2], o3[nt][rh * 2 + 1]);
            }
        __syncthreads();
    }
}

extern "C" void kernel_launch(void* const* d_in, const int* in_sizes, int n_in,
                              void* d_out, int out_size)
{
    const float* Q = (const float*)d_in[0];
    const float* K = (const float*)d_in[1];
    const float* V = (const float*)d_in[2];
    float* out = (float*)d_out;

    const int b = in_sizes[0] / (Tt * Ee);
    const long out_elems = (long)b * Tt * Ee;
    const long a_elems   = (long)b * Tt * BSz;
    float* Afl = ((long)out_size >= out_elems + a_elems) ? (out + out_elems) : nullptr;

    cudaFuncSetAttribute(diag_block_attn_mma,
                         cudaFuncAttributeMaxDynamicSharedMemorySize, SMEM_BYTES);
    dim3 grid(NBk, b);
    diag_block_attn_mma<<<grid, NT, SMEM_BYTES>>>(Q, K, V, out, Afl);
}

// round 11
// speedup vs baseline: 1.5629x; 1.3019x over previous
#include <cuda_runtime.h>
#include <cuda_fp16.h>
#include <cstdint>
#include <math.h>

// DiagBlockAttention b=16,t=8192,e=256,block=128 — mma.sync fp16 single-pass.
// R11: R10 structure (16-row warp bands, register A-frags, shuffle softmax,
// dual causal skip, cp.async phase-1, double-buffered V) with the bf16 hi/lo
// 3-pass replaced by fp16 1-pass (11 mantissa bits, fp32 accumulate).
// d_out = O [b,t,256] fp32 ++ A_flat [b,t,128] fp32.

namespace {
constexpr int Tt = 8192, Ee = 256, BSz = 128, NBk = 64;
constexpr float SCALE = 0.0625f;
constexpr int EC = 32;           // phase-1 e-chunk
constexpr int VC = 32;           // phase-3 e-chunk
constexpr int NT = 256;

// SMEM byte map
// fp16 Q/K tiles [128 r][32 c], 64B rows (swz64), single buffer:
//   Qh +0, Kh +8192  (16 KB)
constexpr int BF0  = 0;
// raw fp32 staging, double-buffered: RAW0 + bs*32768 (Q +0, K +16384)
constexpr int RAW0 = 16384;
// phase 3: V^T fp16 [32 e][128 tok], 256B rows (swz256), double buffered at
//   VB0 + bs*8192 — overlays raw[0] (dead after phase-1 c=6 barriers)
constexpr int VB0  = 16384;
constexpr int SMEM_BYTES = RAW0 + 65536;   // 80 KB -> 2 CTAs/SM
}

__device__ __forceinline__ uint32_t swz64(uint32_t o)  { return o ^ ((o >> 3) & 0x30u); }
__device__ __forceinline__ uint32_t swz256(uint32_t o) { return o ^ ((o >> 4) & 0x70u); }

__device__ __forceinline__ uint32_t smem_u32(const void* p) {
    uint32_t a;
    asm("{ .reg .u64 t; cvta.to.shared.u64 t, %1; cvt.u32.u64 %0, t; }" : "=r"(a) : "l"(p));
    return a;
}

__device__ __forceinline__ void cpasync16(uint32_t dst, const void* src) {
    asm volatile("cp.async.ca.shared.global [%0], [%1], 16;" :: "r"(dst), "l"(src) : "memory");
}
__device__ __forceinline__ void cpcommit() {
    asm volatile("cp.async.commit_group;" ::: "memory");
}
template <int N>
__device__ __forceinline__ void cpwait() {
    asm volatile("cp.async.wait_group %0;" :: "n"(N) : "memory");
}

__device__ __forceinline__ void ldmx4(uint32_t r[4], uint32_t addr) {
    asm volatile("ldmatrix.sync.aligned.m8n8.x4.shared.b16 {%0,%1,%2,%3}, [%4];"
                 : "=r"(r[0]), "=r"(r[1]), "=r"(r[2]), "=r"(r[3]) : "r"(addr));
}

__device__ __forceinline__ void mma16816(float c[4], const uint32_t a[4],
                                         uint32_t b0, uint32_t b1) {
    asm volatile("mma.sync.aligned.m16n8k16.row.col.f32.f16.f16.f32 "
                 "{%0,%1,%2,%3},{%4,%5,%6,%7},{%8,%9},{%0,%1,%2,%3};"
                 : "+f"(c[0]), "+f"(c[1]), "+f"(c[2]), "+f"(c[3])
                 : "r"(a[0]), "r"(a[1]), "r"(a[2]), "r"(a[3]), "r"(b0), "r"(b1));
}

// Pack two fp32 into fp16x2 (lo = x, hi = y), round-to-nearest.
__device__ __forceinline__ uint32_t packh2(float x, float y) {
    uint32_t r;
    asm("cvt.rn.f16x2.f32 %0, %1, %2;" : "=r"(r) : "f"(y), "f"(x));
    return r;
}

__global__ void __launch_bounds__(NT, 2)
diag_block_attn_mma(const float* __restrict__ Q, const float* __restrict__ K,
                    const float* __restrict__ V, float* __restrict__ Out,
                    float* __restrict__ Afl)
{
    extern __shared__ char smc[];
    const uint32_t sb = smem_u32(smc);

    const int tid = threadIdx.x;
    const int wid = tid >> 5;        // 0..7
    const int lid = tid & 31;
    const int g   = lid >> 2;
    const int tg  = lid & 3;
    const int wm  = wid;             // warp row band: rows wm*16..+15
    const int lr  = lid & 15;
    const int lc  = (lid >> 4) * 8;  // ldmatrix col-block (elements)
    const int n   = blockIdx.x;
    const int b   = blockIdx.y;
    const long base = ((long)b * Tt + (long)n * BSz) * Ee;

    // Causal: 16-wide col-tile ng kept iff ng <= wm (also phase-3 k-tiles).
    const int ngEnd = wm + 1;

    // ---- phase-1: cp.async raw fp32 chunk c -> raw buffer bs ----
    auto cpstage1 = [&](int c, int bs) {
        const float* Qg = Q + base + c * EC;
        const float* Kg = K + base + c * EC;
        const uint32_t rw = sb + RAW0 + bs * 32768;
        #pragma unroll
        for (int u = 0; u < 4; ++u) {
            int idx = tid + NT * u;        // 0..1023
            int r   = idx >> 3;            // 0..127
            int s   = idx & 7;             // 16B segment
            cpasync16(rw + r * 128 + s * 16,         Qg + (long)r * Ee + s * 4);
            cpasync16(rw + 16384 + r * 128 + s * 16, Kg + (long)r * Ee + s * 4);
        }
        cpcommit();
    };

    // ---- phase-1: convert raw buffer bs -> fp16 tiles ----
    auto convert1 = [&](int bs) {
        const char* rw = smc + RAW0 + bs * 32768;
        #pragma unroll
        for (int u = 0; u < 4; ++u) {
            int idx = tid + NT * u;        // 0..1023
            int r   = idx >> 3;
            int ce  = (idx & 7) << 2;
            float4 q = *reinterpret_cast<const float4*>(rw + r * 128 + ce * 4);
            float4 k = *reinterpret_cast<const float4*>(rw + 16384 + r * 128 + ce * 4);
            uint32_t off = swz64((uint32_t)(r * 64 + ce * 2));
            *reinterpret_cast<uint2*>(smc + BF0 + off) =
                make_uint2(packh2(q.x, q.y), packh2(q.z, q.w));
            *reinterpret_cast<uint2*>(smc + BF0 + 8192 + off) =
                make_uint2(packh2(k.x, k.y), packh2(k.z, k.w));
        }
    };

    // ---- phase-3 V staging: chunk nc (32 e) -> buffer bs (transposed) ----
    auto stage3 = [&](int nc, int bs) {
        char* bb = smc + VB0 + bs * 8192;
        #pragma unroll
        for (int u = 0; u < 2; ++u) {
            int unit = tid + NT * u;        // 0..511
            int l    = unit & 31;
            int grp  = unit >> 5;           // 0..15
            int c4i  = grp & 7, khi = grp >> 3;
            int k    = 2 * l + 64 * khi;    // even token
            int e0   = 4 * c4i;
            const float* vg = V + base + (long)k * Ee + nc * VC + e0;
            float4 v0 = *reinterpret_cast<const float4*>(vg);
            float4 v1 = *reinterpret_cast<const float4*>(vg + Ee);
            const float* a0 = reinterpret_cast<const float*>(&v0);
            const float* a1 = reinterpret_cast<const float*>(&v1);
            #pragma unroll
            for (int j = 0; j < 4; ++j) {
                uint32_t off = swz256((uint32_t)((e0 + j) * 256 + k * 2));
                *reinterpret_cast<uint32_t*>(bb + off) = packh2(a0[j], a1[j]);
            }
        }
    };

    // ================= Phase 1: S = Q K^T (fp16, cp.async pipe) =============
    float acc[16][4];
    #pragma unroll
    for (int nt = 0; nt < 16; ++nt)
        #pragma unroll
        for (int cc = 0; cc < 4; ++cc) acc[nt][cc] = 0.f;

    cpstage1(0, 0);
    #pragma unroll 1
    for (int c = 0; c < 8; ++c) {
        if (c + 1 < 8) { cpstage1(c + 1, (c + 1) & 1); cpwait<1>(); }
        else           { cpwait<0>(); }
        __syncthreads();   // all warps done with prior MMA (fp16 buf reusable)
        convert1(c & 1);
        __syncthreads();   // fp16 tiles ready
        const uint32_t bb = sb + BF0;
        #pragma unroll
        for (int ks = 0; ks < 2; ++ks) {
            const int colB = (lc + ks * 16) * 2;
            uint32_t qf[4];
            ldmx4(qf, bb + swz64((uint32_t)((wm * 16 + lr) * 64 + colB)));
            #pragma unroll
            for (int ng = 0; ng < 8; ++ng) {
                if (ng < ngEnd) {
                    uint32_t k4[4];
                    ldmx4(k4, bb + 8192 + swz64((uint32_t)((ng * 16 + lr) * 64 + colB)));
                    mma16816(acc[2 * ng],     qf, k4[0], k4[2]);
                    mma16816(acc[2 * ng + 1], qf, k4[1], k4[3]);
                }
            }
        }
    }

    // ================= Phase 2: shuffle-only softmax =================
    const int nValid = 2 * ngEnd;    // live n8-tiles for this warp
    float rmax[2] = {-INFINITY, -INFINITY};
    #pragma unroll
    for (int nt = 0; nt < 16; ++nt) {
        if (nt < nValid) {
            #pragma unroll
            for (int cc = 0; cc < 4; ++cc) {
                int row = wm * 16 + (cc >> 1) * 8 + g;
                int col = nt * 8 + 2 * tg + (cc & 1);
                float v = (col <= row) ? acc[nt][cc] * SCALE : -INFINITY;
                acc[nt][cc] = v;
                rmax[cc >> 1] = fmaxf(rmax[cc >> 1], v);
            }
        }
    }
    #pragma unroll
    for (int rh = 0; rh < 2; ++rh) {
        rmax[rh] = fmaxf(rmax[rh], __shfl_xor_sync(0xffffffffu, rmax[rh], 1));
        rmax[rh] = fmaxf(rmax[rh], __shfl_xor_sync(0xffffffffu, rmax[rh], 2));
    }
    float rsum[2] = {0.f, 0.f};
    #pragma unroll
    for (int nt = 0; nt < 16; ++nt) {
        if (nt < nValid) {
            #pragma unroll
            for (int cc = 0; cc < 4; ++cc) {
                float p = __expf(acc[nt][cc] - rmax[cc >> 1]);
                acc[nt][cc] = p;
                rsum[cc >> 1] += p;
            }
        } else {
            #pragma unroll
            for (int cc = 0; cc < 4; ++cc) acc[nt][cc] = 0.f;
        }
    }
    #pragma unroll
    for (int rh = 0; rh < 2; ++rh) {
        rsum[rh] += __shfl_xor_sync(0xffffffffu, rsum[rh], 1);
        rsum[rh] += __shfl_xor_sync(0xffffffffu, rsum[rh], 2);
    }
    const float rinv[2] = {1.f / rsum[0], 1.f / rsum[1]};

    // Pre-stage V chunk 0 (VB0 = raw[0], dead since the c=7 barriers).
    stage3(0, 0);

    // Normalize; A -> gmem (fp32) and fp16 A-operand fragments IN REGISTERS
    // (C-frag layout == row-major A-frag layout for m16n8k16).
    uint32_t Af[8][4];
    #pragma unroll
    for (int t = 0; t < 8; ++t) {
        #pragma unroll
        for (int half = 0; half < 2; ++half) {
            int nt = 2 * t + half;
            #pragma unroll
            for (int rh = 0; rh < 2; ++rh) {
                float a0 = acc[nt][rh * 2]     * rinv[rh];
                float a1 = acc[nt][rh * 2 + 1] * rinv[rh];
                Af[t][half * 2 + rh] = packh2(a0, a1);
                if (Afl) {
                    int row = wm * 16 + rh * 8 + g;
                    int col = nt * 8 + 2 * tg;
                    *reinterpret_cast<float2*>(
                        Afl + ((long)b * Tt + (long)n * BSz + row) * BSz + col) =
                        make_float2(a0, a1);
                }
            }
        }
    }
    __syncthreads();   // V chunk 0 staged (and all warps past phase-1 reads)

    // ================= Phase 3: O = A V (8 e-chunks of 32, pipelined) ========
    // Warp wm: rows wm*16..+15, all 32 e of the chunk; skip zero A k-tiles.
    #pragma unroll 1
    for (int nc = 0; nc < 8; ++nc) {
        if (nc + 1 < 8) stage3(nc + 1, (nc + 1) & 1);
        const uint32_t vb = sb + VB0 + (nc & 1) * 8192;

        float o3[4][4];
        #pragma unroll
        for (int nt = 0; nt < 4; ++nt)
            #pragma unroll
            for (int cc = 0; cc < 4; ++cc) o3[nt][cc] = 0.f;

        #pragma unroll
        for (int ks = 0; ks < 8; ++ks) {
            if (ks < ngEnd) {
                const int colB = (lc + ks * 16) * 2;
                #pragma unroll
                for (int et = 0; et < 2; ++et) {
                    uint32_t v4[4];
                    ldmx4(v4, vb + swz256((uint32_t)((et * 16 + lr) * 256 + colB)));
                    mma16816(o3[2 * et],     Af[ks], v4[0], v4[2]);
                    mma16816(o3[2 * et + 1], Af[ks], v4[1], v4[3]);
                }
            }
        }

        #pragma unroll
        for (int nt = 0; nt < 4; ++nt)
            #pragma unroll
            for (int rh = 0; rh < 2; ++rh) {
                int row = wm * 16 + rh * 8 + g;
                int col = nc * VC + nt * 8 + 2 * tg;
                *reinterpret_cast<float2*>(Out + base + (long)row * Ee + col) =
                    make_float2(o3[nt][rh * 2], o3[nt][rh * 2 + 1]);
            }
        __syncthreads();
    }
}

extern "C" void kernel_launch(void* const* d_in, const int* in_sizes, int n_in,
                              void* d_out, int out_size)
{
    const float* Q = (const float*)d_in[0];
    const float* K = (const float*)d_in[1];
    const float* V = (const float*)d_in[2];
    float* out = (float*)d_out;

    const int b = in_sizes[0] / (Tt * Ee);
    const long out_elems = (long)b * Tt * Ee;
    const long a_elems   = (long)b * Tt * BSz;
    float* Afl = ((long)out_size >= out_elems + a_elems) ? (out + out_elems) : nullptr;

    cudaFuncSetAttribute(diag_block_attn_mma,
                         cudaFuncAttributeMaxDynamicSharedMemorySize, SMEM_BYTES);
    dim3 grid(NBk, b);
    diag_block_attn_mma<<<grid, NT, SMEM_BYTES>>>(Q, K, V, out, Afl);
}